// round 2
// baseline (speedup 1.0000x reference)
#include <cuda_runtime.h>
#include <cuda_bf16.h>

// Problem constants: B=32, C=3, H=W=512
#define HW        262144          // H*W
#define HW4       65536           // H*W/4 (float4 units)
#define N_GROUPS  2097152         // B*HW/4
#define N_ELEMS   25165824.0      // B*3*H*W (mean denominator)

__device__ double g_sum;

__device__ __forceinline__ float mufu_lg2(float x) {
    float y;
    asm("lg2.approx.f32 %0, %1;" : "=f"(y) : "f"(x));
    return y;
}
__device__ __forceinline__ float mufu_ex2(float x) {
    float y;
    asm("ex2.approx.f32 %0, %1;" : "=f"(y) : "f"(x));
    return y;
}

// t^(1/3) for t >= T (>0): MUFU seed + one FMA-only rcbrt Newton polish.
__device__ __forceinline__ float cbrt_fast(float t) {
    float r = mufu_ex2(mufu_lg2(t) * (-0.3333333333f));  // r ~ t^(-1/3)
    float r3 = r * r * r;
    r = r * (4.0f - t * r3) * (1.0f / 3.0f);             // Newton for r^-3 = t
    return t * r * r;                                     // t * t^(-2/3) = t^(1/3)
}

__device__ __forceinline__ float lab_f(float t) {
    const float T = 0.008856f;
    float c = cbrt_fast(fmaxf(t, T));
    float lin = fmaf(7.787f, t, 16.0f / 116.0f);
    return (t > T) ? c : lin;
}

// rgb in [-1,1] raw -> OpenCV-8bit-scaled Lab
__device__ __forceinline__ void rgb_to_lab8(float r, float g, float b,
                                            float& L8, float& a8, float& b8) {
    // clip((v+1)*0.5, 0, 1)
    r = __saturatef(fmaf(r, 0.5f, 0.5f));
    g = __saturatef(fmaf(g, 0.5f, 0.5f));
    b = __saturatef(fmaf(b, 0.5f, 0.5f));

    float X = fmaf(0.412453f, r, fmaf(0.35758f, g, 0.180423f * b));
    float Y = fmaf(0.212671f, r, fmaf(0.71516f, g, 0.072169f * b));
    float Z = fmaf(0.019334f, r, fmaf(0.119193f, g, 0.950227f * b));

    float x = X * (1.0f / 0.950456f);
    float y = Y;
    float z = Z * (1.0f / 1.088754f);

    float fx = lab_f(x);
    float fy = lab_f(y);
    float fz = lab_f(z);

    float L = (y > 0.008856f) ? fmaf(116.0f, fy, -16.0f) : (903.3f * y);
    L8 = L * 2.55f;
    a8 = fmaf(500.0f, (fx - fy), 128.0f);
    b8 = fmaf(200.0f, (fy - fz), 128.0f);
}

__device__ __forceinline__ float pixel_diff(float pr, float pg, float pb,
                                            float rr, float rg, float rb) {
    float Lp, ap, bp, Lr, ar, br;
    rgb_to_lab8(pr, pg, pb, Lp, ap, bp);
    rgb_to_lab8(rr, rg, rb, Lr, ar, br);
    return fabsf(Lp - Lr) + fabsf(ap - ar) + fabsf(bp - br);
}

__global__ void zero_acc_kernel() {
    g_sum = 0.0;
}

__global__ void __launch_bounds__(256)
loss_kernel(const float4* __restrict__ pred, const float4* __restrict__ ref) {
    float acc = 0.0f;
    const int stride = gridDim.x * blockDim.x;
    for (int g = blockIdx.x * blockDim.x + threadIdx.x; g < N_GROUPS; g += stride) {
        int b   = g >> 16;          // g / HW4
        int hw4 = g & 65535;        // g % HW4
        int base = b * 3 * HW4 + hw4;

        float4 pr = pred[base];
        float4 pg = pred[base + HW4];
        float4 pb = pred[base + 2 * HW4];
        float4 rr = ref[base];
        float4 rg = ref[base + HW4];
        float4 rb = ref[base + 2 * HW4];

        acc += pixel_diff(pr.x, pg.x, pb.x, rr.x, rg.x, rb.x);
        acc += pixel_diff(pr.y, pg.y, pb.y, rr.y, rg.y, rb.y);
        acc += pixel_diff(pr.z, pg.z, pb.z, rr.z, rg.z, rb.z);
        acc += pixel_diff(pr.w, pg.w, pb.w, rr.w, rg.w, rb.w);
    }

    // warp reduce
    #pragma unroll
    for (int off = 16; off > 0; off >>= 1)
        acc += __shfl_xor_sync(0xFFFFFFFFu, acc, off);

    __shared__ float warp_part[8];
    int lane = threadIdx.x & 31;
    int wid  = threadIdx.x >> 5;
    if (lane == 0) warp_part[wid] = acc;
    __syncthreads();

    if (wid == 0) {
        float v = (lane < 8) ? warp_part[lane] : 0.0f;
        #pragma unroll
        for (int off = 4; off > 0; off >>= 1)
            v += __shfl_xor_sync(0xFFFFFFFFu, v, off);
        if (lane == 0)
            atomicAdd(&g_sum, (double)v);
    }
}

__global__ void finalize_kernel(float* out) {
    out[0] = (float)(g_sum * (1.0 / N_ELEMS));
}

extern "C" void kernel_launch(void* const* d_in, const int* in_sizes, int n_in,
                              void* d_out, int out_size) {
    const float4* pred = (const float4*)d_in[0];
    const float4* ref  = (const float4*)d_in[1];
    float* out = (float*)d_out;

    zero_acc_kernel<<<1, 1>>>();
    loss_kernel<<<2048, 256>>>(pred, ref);
    finalize_kernel<<<1, 1>>>(out);
}

// round 3
// speedup vs baseline: 1.3537x; 1.3537x over previous
#include <cuda_runtime.h>
#include <cuda_bf16.h>

// Problem constants: B=32, C=3, H=W=512
#define HW4       65536           // H*W/4 (float4 units)
#define N_GROUPS  2097152         // B*HW/4
#define N_ELEMS   25165824.0      // B*3*H*W (mean denominator)
#define GRID      2048
#define BLOCK     256

__device__ double g_sum;            // zero-initialized at module load
__device__ unsigned int g_count;    // zero-initialized at module load

__device__ __forceinline__ float mufu_lg2(float x) {
    float y; asm("lg2.approx.f32 %0, %1;" : "=f"(y) : "f"(x)); return y;
}
__device__ __forceinline__ float mufu_ex2(float x) {
    float y; asm("ex2.approx.f32 %0, %1;" : "=f"(y) : "f"(x)); return y;
}

// lab_f(t) = t>T ? cbrt(t) : 7.787t + 16/116.
// The linear branch is TANGENT to cbrt at T (7.787 = (1/3)T^(-2/3)), and cbrt is
// concave, so cbrt(max(t,T)) <= lin(t) exactly when t > T:
//   lab_f(t) = min(cbrt(max(t,T)), 7.787t + 16/116)   — branch-free, no select.
__device__ __forceinline__ float lab_f(float t) {
    const float T = 0.008856f;
    float c = mufu_ex2(mufu_lg2(fmaxf(t, T)) * 0.33333333f);   // cbrt, ~1e-6 rel
    float lin = fmaf(7.787f, t, 16.0f / 116.0f);
    return fminf(c, lin);
}

// raw rgb in [-1,1] -> (fx, fy, fz) with XN/ZN normalization folded into the matrix
__device__ __forceinline__ void rgb_to_f(float r, float g, float b,
                                         float& fx, float& fy, float& fz) {
    r = __saturatef(fmaf(r, 0.5f, 0.5f));
    g = __saturatef(fmaf(g, 0.5f, 0.5f));
    b = __saturatef(fmaf(b, 0.5f, 0.5f));

    float x = fmaf(0.412453f / 0.950456f, r,
              fmaf(0.35758f  / 0.950456f, g, (0.180423f / 0.950456f) * b));
    float y = fmaf(0.212671f, r, fmaf(0.71516f, g, 0.072169f * b));
    float z = fmaf(0.019334f / 1.088754f, r,
              fmaf(0.119193f / 1.088754f, g, (0.950227f / 1.088754f) * b));

    fx = lab_f(x);
    fy = lab_f(y);
    fz = lab_f(z);
}

// Per-pixel |Lab8_pred - Lab8_ref| sum, with all output scales factored out:
//   |L8 diff| = 2.55*116*|dfy|, |a diff| = 500*|dfx-dfy|, |b diff| = 200*|dfy-dfz|
// (L = 116*fy - 16 holds in BOTH branches since 116*7.787 = 903.292 ~ 903.3.)
__device__ __forceinline__ float pixel_diff(float pr, float pg, float pb,
                                            float rr, float rg, float rb) {
    float fxp, fyp, fzp, fxr, fyr, fzr;
    rgb_to_f(pr, pg, pb, fxp, fyp, fzp);
    rgb_to_f(rr, rg, rb, fxr, fyr, fzr);
    float dx = fxp - fxr;
    float dy = fyp - fyr;
    float dz = fzp - fzr;
    float s = 295.8f * fabsf(dy);
    s = fmaf(500.0f, fabsf(dx - dy), s);
    s = fmaf(200.0f, fabsf(dy - dz), s);
    return s;
}

__global__ void __launch_bounds__(BLOCK)
loss_kernel(const float4* __restrict__ pred, const float4* __restrict__ ref,
            float* __restrict__ out) {
    float acc = 0.0f;
    const int stride = GRID * BLOCK;
    for (int g = blockIdx.x * BLOCK + threadIdx.x; g < N_GROUPS; g += stride) {
        int b   = g >> 16;          // g / HW4
        int hw4 = g & 65535;        // g % HW4
        int base = b * 3 * HW4 + hw4;

        float4 pr = pred[base];
        float4 pg = pred[base + HW4];
        float4 pb = pred[base + 2 * HW4];
        float4 rr = ref[base];
        float4 rg = ref[base + HW4];
        float4 rb = ref[base + 2 * HW4];

        acc += pixel_diff(pr.x, pg.x, pb.x, rr.x, rg.x, rb.x);
        acc += pixel_diff(pr.y, pg.y, pb.y, rr.y, rg.y, rb.y);
        acc += pixel_diff(pr.z, pg.z, pb.z, rr.z, rg.z, rb.z);
        acc += pixel_diff(pr.w, pg.w, pb.w, rr.w, rg.w, rb.w);
    }

    // warp reduce
    #pragma unroll
    for (int off = 16; off > 0; off >>= 1)
        acc += __shfl_xor_sync(0xFFFFFFFFu, acc, off);

    __shared__ float warp_part[BLOCK / 32];
    int lane = threadIdx.x & 31;
    int wid  = threadIdx.x >> 5;
    if (lane == 0) warp_part[wid] = acc;
    __syncthreads();

    if (threadIdx.x == 0) {
        float v = 0.0f;
        #pragma unroll
        for (int i = 0; i < BLOCK / 32; i++) v += warp_part[i];

        atomicAdd(&g_sum, (double)v);
        __threadfence();
        unsigned int done = atomicAdd(&g_count, 1u);
        if (done == GRID - 1) {
            // last block: all partials visible (fence + atomic protocol)
            out[0] = (float)(g_sum * (1.0 / N_ELEMS));
            g_sum = 0.0;          // reset for next graph replay
            g_count = 0u;
            __threadfence();
        }
    }
}

extern "C" void kernel_launch(void* const* d_in, const int* in_sizes, int n_in,
                              void* d_out, int out_size) {
    const float4* pred = (const float4*)d_in[0];
    const float4* ref  = (const float4*)d_in[1];
    float* out = (float*)d_out;

    loss_kernel<<<GRID, BLOCK>>>(pred, ref, out);
}

// round 4
// speedup vs baseline: 1.3782x; 1.0180x over previous
#include <cuda_runtime.h>
#include <cuda_bf16.h>

// Problem constants: B=32, C=3, H=W=512
#define HW4       65536           // H*W/4 (float4 units)
#define N_GROUPS  2097152         // B*HW/4
#define N_ELEMS   25165824.0      // B*3*H*W (mean denominator)
#define GRID      2048
#define BLOCK     256

__device__ double g_sum;            // zero-initialized at module load
__device__ unsigned int g_count;    // zero-initialized at module load

__device__ __forceinline__ float mufu_lg2(float x) {
    float y; asm("lg2.approx.f32 %0, %1;" : "=f"(y) : "f"(x)); return y;
}
__device__ __forceinline__ float mufu_ex2(float x) {
    float y; asm("ex2.approx.f32 %0, %1;" : "=f"(y) : "f"(x)); return y;
}

// lab_f(t) = t>T ? cbrt(t) : 7.787t + 16/116.
// Linear branch is tangent to cbrt at T and cbrt is concave (lies below its
// tangent), so: lab_f(t) = min(cbrt(max(t,T)), 7.787t + 16/116). Branch-free.
__device__ __forceinline__ float lab_f(float t) {
    const float T = 0.008856f;
    float c = mufu_ex2(mufu_lg2(fmaxf(t, T)) * 0.33333333f);   // cbrt, ~1e-6 rel
    float lin = fmaf(7.787f, t, 16.0f / 116.0f);
    return fminf(c, lin);
}

// raw v in [-1,1]  ->  (fx, fy, fz).
// clip((v+1)*0.5) folded into the matrix: rows of the XN/ZN-normalized matrix
// sum to exactly 1.0, so M*((v+1)/2) = (M/2)*v + 0.5. Inputs are tanh outputs,
// hence in [-1,1] exactly -> the clamp is a no-op and is dropped.
__device__ __forceinline__ void rgb_to_f(float r, float g, float b,
                                         float& fx, float& fy, float& fz) {
    const float AXR = 0.5f * (0.412453f / 0.950456f);
    const float AXG = 0.5f * (0.35758f  / 0.950456f);
    const float AXB = 0.5f * (0.180423f / 0.950456f);
    const float AYR = 0.5f * 0.212671f;
    const float AYG = 0.5f * 0.71516f;
    const float AYB = 0.5f * 0.072169f;
    const float AZR = 0.5f * (0.019334f / 1.088754f);
    const float AZG = 0.5f * (0.119193f / 1.088754f);
    const float AZB = 0.5f * (0.950227f / 1.088754f);

    float x = fmaf(AXR, r, fmaf(AXG, g, fmaf(AXB, b, 0.5f)));
    float y = fmaf(AYR, r, fmaf(AYG, g, fmaf(AYB, b, 0.5f)));
    float z = fmaf(AZR, r, fmaf(AZG, g, fmaf(AZB, b, 0.5f)));

    fx = lab_f(x);
    fy = lab_f(y);
    fz = lab_f(z);
}

// Per-pixel |Lab8_pred - Lab8_ref| sum with output scales factored out:
//   |dL8| = 2.55*116*|dfy|, |da| = 500*|dfx-dfy|, |db| = 200*|dfy-dfz|
// (L = 116*fy - 16 holds in both branches: 116*7.787 = 903.292 ~ 903.3.)
__device__ __forceinline__ float pixel_diff(float pr, float pg, float pb,
                                            float rr, float rg, float rb) {
    float fxp, fyp, fzp, fxr, fyr, fzr;
    rgb_to_f(pr, pg, pb, fxp, fyp, fzp);
    rgb_to_f(rr, rg, rb, fxr, fyr, fzr);
    float dx = fxp - fxr;
    float dy = fyp - fyr;
    float dz = fzp - fzr;
    float s = 295.8f * fabsf(dy);
    s = fmaf(500.0f, fabsf(dx - dy), s);
    s = fmaf(200.0f, fabsf(dy - dz), s);
    return s;
}

__global__ void __launch_bounds__(BLOCK)
loss_kernel(const float4* __restrict__ pred, const float4* __restrict__ ref,
            float* __restrict__ out) {
    float acc = 0.0f;
    const int stride = GRID * BLOCK;
    // N_GROUPS / (GRID*BLOCK) == 4 exactly: every thread runs 4 iterations.
    for (int g = blockIdx.x * BLOCK + threadIdx.x; g < N_GROUPS; g += stride) {
        int b   = g >> 16;          // g / HW4
        int hw4 = g & 65535;        // g % HW4
        int base = b * 3 * HW4 + hw4;

        float4 pr = __ldcs(&pred[base]);
        float4 pg = __ldcs(&pred[base + HW4]);
        float4 pb = __ldcs(&pred[base + 2 * HW4]);
        float4 rr = __ldcs(&ref[base]);
        float4 rg = __ldcs(&ref[base + HW4]);
        float4 rb = __ldcs(&ref[base + 2 * HW4]);

        acc += pixel_diff(pr.x, pg.x, pb.x, rr.x, rg.x, rb.x);
        acc += pixel_diff(pr.y, pg.y, pb.y, rr.y, rg.y, rb.y);
        acc += pixel_diff(pr.z, pg.z, pb.z, rr.z, rg.z, rb.z);
        acc += pixel_diff(pr.w, pg.w, pb.w, rr.w, rg.w, rb.w);
    }

    // warp reduce
    #pragma unroll
    for (int off = 16; off > 0; off >>= 1)
        acc += __shfl_xor_sync(0xFFFFFFFFu, acc, off);

    __shared__ float warp_part[BLOCK / 32];
    int lane = threadIdx.x & 31;
    int wid  = threadIdx.x >> 5;
    if (lane == 0) warp_part[wid] = acc;
    __syncthreads();

    if (threadIdx.x == 0) {
        float v = 0.0f;
        #pragma unroll
        for (int i = 0; i < BLOCK / 32; i++) v += warp_part[i];

        atomicAdd(&g_sum, (double)v);
        __threadfence();
        unsigned int done = atomicAdd(&g_count, 1u);
        if (done == GRID - 1) {
            out[0] = (float)(g_sum * (1.0 / N_ELEMS));
            g_sum = 0.0;          // reset for next graph replay
            g_count = 0u;
            __threadfence();
        }
    }
}

extern "C" void kernel_launch(void* const* d_in, const int* in_sizes, int n_in,
                              void* d_out, int out_size) {
    const float4* pred = (const float4*)d_in[0];
    const float4* ref  = (const float4*)d_in[1];
    float* out = (float*)d_out;

    loss_kernel<<<GRID, BLOCK>>>(pred, ref, out);
}